// round 1
// baseline (speedup 1.0000x reference)
#include <cuda_runtime.h>
#include <math.h>

#define EMBED 1024
#define NHEADS 16
#define HD 64
#define BB 2
#define SS 2048
#define BHD (BB*NHEADS)   // 32
#define MROWS (BB*SS)     // 4096

// Scratch for projected Q,K,V in [B,H,S,D] layout (device globals: alloc-guard safe)
__device__ float g_Q[(size_t)BB*NHEADS*SS*HD];
__device__ float g_K[(size_t)BB*NHEADS*SS*HD];
__device__ float g_V[(size_t)BB*NHEADS*SS*HD];

// ---------------------------------------------------------------------------
// Kernel 1: fused QKV projection.  y = x @ W^T + b, written as [B,H,S,D].
// Tiles: BM=BN=64, BK=16. 256 threads, each computes a 4x4 micro-tile.
// ---------------------------------------------------------------------------
__global__ void __launch_bounds__(256) proj_kernel(
    const float* __restrict__ xq, const float* __restrict__ xk, const float* __restrict__ xv,
    const float* __restrict__ Wq, const float* __restrict__ Wk, const float* __restrict__ Wv,
    const float* __restrict__ bq, const float* __restrict__ bk, const float* __restrict__ bv)
{
    __shared__ float As[16][68];  // As[k][m]
    __shared__ float Bs[16][68];  // Bs[k][n]

    const float* x; const float* W; const float* bias; float* out;
    int z = blockIdx.z;
    if (z == 0)      { x = xq; W = Wq; bias = bq; out = g_Q; }
    else if (z == 1) { x = xk; W = Wk; bias = bk; out = g_K; }
    else             { x = xv; W = Wv; bias = bv; out = g_V; }

    const int m0 = blockIdx.y * 64;
    const int n0 = blockIdx.x * 64;
    const int t  = threadIdx.x;
    const int tx = t & 15;
    const int ty = t >> 4;

    const int lrow = t >> 2;       // 0..63
    const int lk4  = (t & 3) * 4;  // 0,4,8,12

    float acc[4][4];
    #pragma unroll
    for (int i = 0; i < 4; i++)
        #pragma unroll
        for (int j = 0; j < 4; j++) acc[i][j] = 0.f;

    for (int k0 = 0; k0 < EMBED; k0 += 16) {
        float4 av = *(const float4*)(x + (size_t)(m0 + lrow) * EMBED + k0 + lk4);
        As[lk4+0][lrow] = av.x; As[lk4+1][lrow] = av.y;
        As[lk4+2][lrow] = av.z; As[lk4+3][lrow] = av.w;
        float4 wv = *(const float4*)(W + (size_t)(n0 + lrow) * EMBED + k0 + lk4);
        Bs[lk4+0][lrow] = wv.x; Bs[lk4+1][lrow] = wv.y;
        Bs[lk4+2][lrow] = wv.z; Bs[lk4+3][lrow] = wv.w;
        __syncthreads();

        #pragma unroll
        for (int k = 0; k < 16; k++) {
            float4 a = *(const float4*)&As[k][ty * 4];
            float4 b = *(const float4*)&Bs[k][tx * 4];
            float ar[4] = {a.x, a.y, a.z, a.w};
            float br[4] = {b.x, b.y, b.z, b.w};
            #pragma unroll
            for (int i = 0; i < 4; i++)
                #pragma unroll
                for (int j = 0; j < 4; j++)
                    acc[i][j] = fmaf(ar[i], br[j], acc[i][j]);
        }
        __syncthreads();
    }

    // Write out: n0 is 64-aligned so the whole block maps to one head h.
    const int h = n0 >> 6;
    #pragma unroll
    for (int i = 0; i < 4; i++) {
        int m = m0 + ty * 4 + i;
        int bb = m / SS, s = m % SS;
        float* orow = out + (((size_t)bb * NHEADS + h) * SS + s) * HD;
        #pragma unroll
        for (int j = 0; j < 4; j++) {
            int d = tx * 4 + j;
            orow[d] = acc[i][j] + bias[n0 + d];
        }
    }
}

// ---------------------------------------------------------------------------
// Kernel 2: flash attention. One block per (b*h, q-tile of 64 rows).
// Loops over 32 key tiles of 64. Online softmax, sentinel -1e30 for mask.
// ---------------------------------------------------------------------------
struct AttnSmem {
    float Qs[64][68];   // Qs[d][r]
    float KPs[64][68];  // union: Ks[d][c] then Ps[c][r]
    float Vs[64][68];   // Vs[c][d]
    float red1[64][16]; // row-max partials
    float red2[64][16]; // row-sum partials
    float maskv[64];    // additive mask for this key tile
};

#define SCALE 0.03125f   // 1/sqrt(1024)
#define NEG_BIG (-1e30f)

__global__ void __launch_bounds__(256) attn_kernel(const int* __restrict__ amask,
                                                   float* __restrict__ out)
{
    extern __shared__ char smem_raw[];
    AttnSmem* sm = (AttnSmem*)smem_raw;

    const int bh = blockIdx.x;            // 0..31
    const int b  = bh / NHEADS;
    const int q0 = blockIdx.y * 64;
    const int t  = threadIdx.x;
    const int tx = t & 15;
    const int ty = t >> 4;

    const float* Qb = g_Q + (size_t)bh * SS * HD;
    const float* Kb = g_K + (size_t)bh * SS * HD;
    const float* Vb = g_V + (size_t)bh * SS * HD;

    // Load Q tile transposed: Qs[d][r]
    #pragma unroll
    for (int it = 0; it < 4; it++) {
        int e  = t + it * 256;     // 0..1023 float4 slots
        int r  = e >> 4;
        int d4 = (e & 15) * 4;
        float4 qv = *(const float4*)(Qb + ((size_t)(q0 + r)) * HD + d4);
        sm->Qs[d4+0][r] = qv.x; sm->Qs[d4+1][r] = qv.y;
        sm->Qs[d4+2][r] = qv.z; sm->Qs[d4+3][r] = qv.w;
    }

    float o[4][4];
    float m_run[4], l_run[4];
    #pragma unroll
    for (int i = 0; i < 4; i++) {
        m_run[i] = NEG_BIG; l_run[i] = 0.f;
        #pragma unroll
        for (int j = 0; j < 4; j++) o[i][j] = 0.f;
    }

    for (int kt = 0; kt < SS / 64; kt++) {
        const int k0 = kt * 64;
        __syncthreads();  // prior iter done with KPs/Vs; Qs store visible on 1st iter

        // Load K tile transposed (Ks[d][c]) and V tile direct (Vs[c][d])
        #pragma unroll
        for (int it = 0; it < 4; it++) {
            int e  = t + it * 256;
            int r  = e >> 4;
            int d4 = (e & 15) * 4;
            float4 kv = *(const float4*)(Kb + ((size_t)(k0 + r)) * HD + d4);
            sm->KPs[d4+0][r] = kv.x; sm->KPs[d4+1][r] = kv.y;
            sm->KPs[d4+2][r] = kv.z; sm->KPs[d4+3][r] = kv.w;
            float4 vv = *(const float4*)(Vb + ((size_t)(k0 + r)) * HD + d4);
            *(float4*)&sm->Vs[r][d4] = vv;
        }
        if (t < 64)
            sm->maskv[t] = (amask[(size_t)b * SS + k0 + t] == 0) ? NEG_BIG : 0.f;
        __syncthreads();

        // S = scale * Q K^T + mask
        float s[4][4];
        #pragma unroll
        for (int i = 0; i < 4; i++)
            #pragma unroll
            for (int j = 0; j < 4; j++) s[i][j] = 0.f;

        #pragma unroll 8
        for (int d = 0; d < 64; d++) {
            float4 a = *(const float4*)&sm->Qs[d][ty * 4];
            float4 bq4 = *(const float4*)&sm->KPs[d][tx * 4];
            float ar[4] = {a.x, a.y, a.z, a.w};
            float br[4] = {bq4.x, bq4.y, bq4.z, bq4.w};
            #pragma unroll
            for (int i = 0; i < 4; i++)
                #pragma unroll
                for (int j = 0; j < 4; j++)
                    s[i][j] = fmaf(ar[i], br[j], s[i][j]);
        }
        float mk[4];
        #pragma unroll
        for (int j = 0; j < 4; j++) mk[j] = sm->maskv[tx * 4 + j];
        #pragma unroll
        for (int i = 0; i < 4; i++)
            #pragma unroll
            for (int j = 0; j < 4; j++)
                s[i][j] = s[i][j] * SCALE + mk[j];

        // row-max partials
        #pragma unroll
        for (int i = 0; i < 4; i++) {
            float rm = fmaxf(fmaxf(s[i][0], s[i][1]), fmaxf(s[i][2], s[i][3]));
            sm->red1[ty * 4 + i][tx] = rm;
        }
        __syncthreads();  // red1 ready; also: all Ks reads done -> KPs reusable as Ps

        float alpha[4], tsum[4];
        #pragma unroll
        for (int i = 0; i < 4; i++) {
            int r = ty * 4 + i;
            float mt = NEG_BIG;
            #pragma unroll
            for (int x = 0; x < 16; x++) mt = fmaxf(mt, sm->red1[r][x]);
            float mnew = fmaxf(m_run[i], mt);
            alpha[i] = __expf(m_run[i] - mnew);
            m_run[i] = mnew;
            float rs = 0.f;
            #pragma unroll
            for (int j = 0; j < 4; j++) {
                float p = __expf(s[i][j] - mnew);
                s[i][j] = p;                         // reuse s as P
                rs += p;
                sm->KPs[tx * 4 + j][r] = p;          // Ps[c][r]
            }
            tsum[i] = rs;
            sm->red2[r][tx] = rs;
        }
        __syncthreads();  // Ps + red2 ready

        #pragma unroll
        for (int i = 0; i < 4; i++) {
            int r = ty * 4 + i;
            float ts = 0.f;
            #pragma unroll
            for (int x = 0; x < 16; x++) ts += sm->red2[r][x];
            l_run[i] = l_run[i] * alpha[i] + ts;
            #pragma unroll
            for (int j = 0; j < 4; j++) o[i][j] *= alpha[i];
        }
        (void)tsum;

        // O += P @ V
        #pragma unroll 8
        for (int c = 0; c < 64; c++) {
            float4 pv = *(const float4*)&sm->KPs[c][ty * 4];
            float4 vv = *(const float4*)&sm->Vs[c][tx * 4];
            float pr[4] = {pv.x, pv.y, pv.z, pv.w};
            float vr[4] = {vv.x, vv.y, vv.z, vv.w};
            #pragma unroll
            for (int i = 0; i < 4; i++)
                #pragma unroll
                for (int j = 0; j < 4; j++)
                    o[i][j] = fmaf(pr[i], vr[j], o[i][j]);
        }
    }

    // Write normalized output: out[B,H,S,D]
    #pragma unroll
    for (int i = 0; i < 4; i++) {
        int r = q0 + ty * 4 + i;
        float inv_l = 1.f / l_run[i];
        float* orow = out + ((size_t)bh * SS + r) * HD;
        #pragma unroll
        for (int j = 0; j < 4; j++)
            orow[tx * 4 + j] = o[i][j] * inv_l;
    }
}

// ---------------------------------------------------------------------------
extern "C" void kernel_launch(void* const* d_in, const int* in_sizes, int n_in,
                              void* d_out, int out_size)
{
    (void)in_sizes; (void)n_in; (void)out_size;
    const float* q  = (const float*)d_in[0];
    const float* k  = (const float*)d_in[1];
    const float* v  = (const float*)d_in[2];
    const int*   am = (const int*)  d_in[3];
    const float* Wq = (const float*)d_in[4];
    const float* bq = (const float*)d_in[5];
    const float* Wk = (const float*)d_in[6];
    const float* bk = (const float*)d_in[7];
    const float* Wv = (const float*)d_in[8];
    const float* bv = (const float*)d_in[9];

    static int attr_set = 0;
    if (!attr_set) {
        cudaFuncSetAttribute(attn_kernel, cudaFuncAttributeMaxDynamicSharedMemorySize,
                             (int)sizeof(AttnSmem));
        attr_set = 1;
    }

    dim3 pgrid(EMBED / 64, MROWS / 64, 3);
    proj_kernel<<<pgrid, 256>>>(q, k, v, Wq, Wk, Wv, bq, bk, bv);

    dim3 agrid(BHD, SS / 64);
    attn_kernel<<<agrid, 256, sizeof(AttnSmem)>>>(am, (float*)d_out);
}

// round 5
// speedup vs baseline: 3.0715x; 3.0715x over previous
#include <cuda_runtime.h>
#include <cstdint>
#include <math.h>

#define EMBED 1024
#define NHEADS 16
#define HD 64
#define BB 2
#define SS 2048
#define BHD (BB*NHEADS)   // 32
#define MROWS (BB*SS)     // 4096
#define SCALE 0.03125f    // 1/sqrt(1024)

// Projected Q,K,V in [B,H,S,D] fp32 (device globals: alloc-guard safe)
__device__ float g_Q[(size_t)BB*NHEADS*SS*HD];
__device__ float g_K[(size_t)BB*NHEADS*SS*HD];
__device__ float g_V[(size_t)BB*NHEADS*SS*HD];

__device__ __forceinline__ float to_tf32(float x) {
    float r;
    asm("cvt.rna.tf32.f32 %0, %1;" : "=f"(r) : "f"(x));
    return r;
}

// D = A(16x8 tf32) * B(8x8 tf32) + D, f32 accum. row.col layout.
__device__ __forceinline__ void mma8(float* d, const uint32_t* a, const uint32_t* b) {
    asm volatile(
        "mma.sync.aligned.m16n8k8.row.col.f32.tf32.tf32.f32 "
        "{%0,%1,%2,%3}, {%4,%5,%6,%7}, {%8,%9}, {%0,%1,%2,%3};"
        : "+f"(d[0]), "+f"(d[1]), "+f"(d[2]), "+f"(d[3])
        : "r"(a[0]), "r"(a[1]), "r"(a[2]), "r"(a[3]), "r"(b[0]), "r"(b[1]));
}

// ---------------------------------------------------------------------------
// Kernel 1: QKV projection  y = x @ W^T + b  -> [B,H,S,D]
// BM=BN=128, BK=32. 8 warps as 2x4, warp tile 64x32. Register prefetch.
// ---------------------------------------------------------------------------
#define PSTR 36   // smem row stride (floats): 32 + 4 pad

__global__ void __launch_bounds__(256) proj_kernel(
    const float* __restrict__ xq, const float* __restrict__ xk, const float* __restrict__ xv,
    const float* __restrict__ Wq, const float* __restrict__ Wk, const float* __restrict__ Wv,
    const float* __restrict__ bq, const float* __restrict__ bk, const float* __restrict__ bv)
{
    __shared__ float As[128 * PSTR];
    __shared__ float Bs[128 * PSTR];

    const float* x; const float* W; const float* bias; float* outp;
    int z = blockIdx.z;
    if (z == 0)      { x = xq; W = Wq; bias = bq; outp = g_Q; }
    else if (z == 1) { x = xk; W = Wk; bias = bk; outp = g_K; }
    else             { x = xv; W = Wv; bias = bv; outp = g_V; }

    const int m0 = blockIdx.y * 128;
    const int n0 = blockIdx.x * 128;
    const int tid  = threadIdx.x;
    const int wid  = tid >> 5;
    const int lane = tid & 31;
    const int g    = lane >> 2;
    const int t4   = lane & 3;
    const int wm   = (wid >> 2) * 64;   // 0 or 64
    const int wn   = (wid & 3) * 32;    // 0,32,64,96

    float4 ra[4], rb[4];

#define PROJ_LOADG(K0)                                                          \
    {                                                                           \
        _Pragma("unroll")                                                       \
        for (int i = 0; i < 4; i++) {                                           \
            int idx = tid + i * 256;                                            \
            int r = idx >> 3, c4 = idx & 7;                                     \
            ra[i] = *(const float4*)(x + (size_t)(m0 + r) * EMBED + (K0) + c4 * 4); \
            rb[i] = *(const float4*)(W + (size_t)(n0 + r) * EMBED + (K0) + c4 * 4); \
        }                                                                       \
    }

    float acc[4][4][4];
    #pragma unroll
    for (int mi = 0; mi < 4; mi++)
        #pragma unroll
        for (int nj = 0; nj < 4; nj++)
            #pragma unroll
            for (int e = 0; e < 4; e++) acc[mi][nj][e] = 0.f;

    PROJ_LOADG(0);

    for (int c = 0; c < EMBED / 32; c++) {
        // stage registers -> smem (with RNA tf32 rounding)
        #pragma unroll
        for (int i = 0; i < 4; i++) {
            int idx = tid + i * 256;
            int r = idx >> 3, c4 = idx & 7;
            float* pa = &As[r * PSTR + c4 * 4];
            pa[0] = to_tf32(ra[i].x); pa[1] = to_tf32(ra[i].y);
            pa[2] = to_tf32(ra[i].z); pa[3] = to_tf32(ra[i].w);
            float* pb = &Bs[r * PSTR + c4 * 4];
            pb[0] = to_tf32(rb[i].x); pb[1] = to_tf32(rb[i].y);
            pb[2] = to_tf32(rb[i].z); pb[3] = to_tf32(rb[i].w);
        }
        __syncthreads();
        if (c + 1 < EMBED / 32) PROJ_LOADG((c + 1) * 32);

        #pragma unroll
        for (int ks = 0; ks < 4; ks++) {
            uint32_t af[4][4], bf[4][2];
            #pragma unroll
            for (int mi = 0; mi < 4; mi++) {
                const float* p = &As[(wm + mi * 16 + g) * PSTR + ks * 8 + t4];
                af[mi][0] = __float_as_uint(p[0]);
                af[mi][1] = __float_as_uint(p[8 * PSTR]);
                af[mi][2] = __float_as_uint(p[4]);
                af[mi][3] = __float_as_uint(p[8 * PSTR + 4]);
            }
            #pragma unroll
            for (int nj = 0; nj < 4; nj++) {
                const float* p = &Bs[(wn + nj * 8 + g) * PSTR + ks * 8 + t4];
                bf[nj][0] = __float_as_uint(p[0]);
                bf[nj][1] = __float_as_uint(p[4]);
            }
            #pragma unroll
            for (int mi = 0; mi < 4; mi++)
                #pragma unroll
                for (int nj = 0; nj < 4; nj++)
                    mma8(acc[mi][nj], af[mi], bf[nj]);
        }
        __syncthreads();
    }

    // epilogue: +bias, scatter to [B,H,S,D]
    #pragma unroll
    for (int mi = 0; mi < 4; mi++) {
        int r0 = m0 + wm + mi * 16 + g;
        int r1 = r0 + 8;
        int bb0 = r0 >> 11, s0 = r0 & 2047;
        int bb1 = r1 >> 11, s1 = r1 & 2047;
        #pragma unroll
        for (int nj = 0; nj < 4; nj++) {
            int f = n0 + wn + nj * 8 + 2 * t4;  // even
            int h = f >> 6, dd = f & 63;
            float b0 = bias[f], b1 = bias[f + 1];
            float* p0 = outp + (((size_t)(bb0 * NHEADS + h)) * SS + s0) * HD + dd;
            float* p1 = outp + (((size_t)(bb1 * NHEADS + h)) * SS + s1) * HD + dd;
            *(float2*)p0 = make_float2(acc[mi][nj][0] + b0, acc[mi][nj][1] + b1);
            *(float2*)p1 = make_float2(acc[mi][nj][2] + b0, acc[mi][nj][3] + b1);
        }
    }
}

// ---------------------------------------------------------------------------
// Kernel 2: attention. Per CTA: (bh, 128 q-rows). 8 warps as 2x4.
// S = Q K^T (regs) -> masked exp (no max-sub) -> P via smem -> O += P V (regs)
// ---------------------------------------------------------------------------
#define ASTR 68   // smem row stride (floats): 64 + 4 pad

// float offsets in dynamic smem
#define OFF_Q   0
#define OFF_K   (OFF_Q + 128 * ASTR)       // 8704
#define OFF_V   (OFF_K + 64 * ASTR)        // 13056
#define OFF_P   (OFF_V + 64 * ASTR)        // 17408
#define OFF_LP  (OFF_P + 128 * ASTR)       // 26112
#define OFF_LR  (OFF_LP + 4 * 128)         // 26624
#define OFF_MK  (OFF_LR + 128)             // 26752
#define ASM_FLOATS (OFF_MK + 64)           // 26816 floats = 107264 B

__global__ void __launch_bounds__(256) attn_kernel(const int* __restrict__ amask,
                                                   float* __restrict__ out)
{
    extern __shared__ float sm[];
    float* Qs    = sm + OFF_Q;
    float* Ks    = sm + OFF_K;
    float* Vs    = sm + OFF_V;
    float* Ps    = sm + OFF_P;
    float* lpart = sm + OFF_LP;
    float* lrun  = sm + OFF_LR;
    float* maskv = sm + OFF_MK;

    const int tid  = threadIdx.x;
    const int wid  = tid >> 5;
    const int lane = tid & 31;
    const int g    = lane >> 2;
    const int t4   = lane & 3;
    const int wm   = (wid >> 2) * 64;
    const int wnid = wid & 3;
    const int wn   = wnid * 16;

    const int bh = blockIdx.x;
    const int b  = bh >> 4;
    const int q0 = blockIdx.y * 128;

    const float* Qb = g_Q + (size_t)bh * SS * HD;
    const float* Kb = g_K + (size_t)bh * SS * HD;
    const float* Vb = g_V + (size_t)bh * SS * HD;

    // load Q tile [128x64] (tf32-rounded)
    #pragma unroll
    for (int i = 0; i < 8; i++) {
        int idx = tid + i * 256;
        int r = idx >> 4, c4 = idx & 15;
        float4 q = *(const float4*)(Qb + (size_t)(q0 + r) * HD + c4 * 4);
        float* p = &Qs[r * ASTR + c4 * 4];
        p[0] = to_tf32(q.x); p[1] = to_tf32(q.y);
        p[2] = to_tf32(q.z); p[3] = to_tf32(q.w);
    }
    if (tid < 128) lrun[tid] = 0.f;

    float4 rk[4], rv[4];
#define ATTN_PREF(KT)                                                           \
    {                                                                           \
        _Pragma("unroll")                                                       \
        for (int i = 0; i < 4; i++) {                                           \
            int idx = tid + i * 256;                                            \
            int r = idx >> 4, c4 = idx & 15;                                    \
            rk[i] = *(const float4*)(Kb + (size_t)((KT) * 64 + r) * HD + c4 * 4); \
            rv[i] = *(const float4*)(Vb + (size_t)((KT) * 64 + r) * HD + c4 * 4); \
        }                                                                       \
    }
    ATTN_PREF(0);

    float oacc[4][2][4];
    #pragma unroll
    for (int mi = 0; mi < 4; mi++)
        #pragma unroll
        for (int nj = 0; nj < 2; nj++)
            #pragma unroll
            for (int e = 0; e < 4; e++) oacc[mi][nj][e] = 0.f;

    for (int kt = 0; kt < SS / 64; kt++) {
        // stage K,V tiles (K: [key][d]; V: [key][d], both direct copies)
        #pragma unroll
        for (int i = 0; i < 4; i++) {
            int idx = tid + i * 256;
            int r = idx >> 4, c4 = idx & 15;
            float* pk = &Ks[r * ASTR + c4 * 4];
            pk[0] = to_tf32(rk[i].x); pk[1] = to_tf32(rk[i].y);
            pk[2] = to_tf32(rk[i].z); pk[3] = to_tf32(rk[i].w);
            float* pv = &Vs[r * ASTR + c4 * 4];
            pv[0] = to_tf32(rv[i].x); pv[1] = to_tf32(rv[i].y);
            pv[2] = to_tf32(rv[i].z); pv[3] = to_tf32(rv[i].w);
        }
        if (tid < 64)
            maskv[tid] = (amask[(size_t)b * SS + kt * 64 + tid] != 0) ? 1.f : 0.f;
        __syncthreads();
        if (kt + 1 < SS / 64) ATTN_PREF(kt + 1);

        // ---- MMA1: S[128x64] = Q K^T (warp tile 64x16) ----
        float sacc[4][2][4];
        #pragma unroll
        for (int mi = 0; mi < 4; mi++)
            #pragma unroll
            for (int nj = 0; nj < 2; nj++)
                #pragma unroll
                for (int e = 0; e < 4; e++) sacc[mi][nj][e] = 0.f;

        #pragma unroll
        for (int ks = 0; ks < 8; ks++) {
            uint32_t af[4][4], bf[2][2];
            #pragma unroll
            for (int mi = 0; mi < 4; mi++) {
                const float* p = &Qs[(wm + mi * 16 + g) * ASTR + ks * 8 + t4];
                af[mi][0] = __float_as_uint(p[0]);
                af[mi][1] = __float_as_uint(p[8 * ASTR]);
                af[mi][2] = __float_as_uint(p[4]);
                af[mi][3] = __float_as_uint(p[8 * ASTR + 4]);
            }
            #pragma unroll
            for (int nj = 0; nj < 2; nj++) {
                const float* p = &Ks[(wn + nj * 8 + g) * ASTR + ks * 8 + t4];
                bf[nj][0] = __float_as_uint(p[0]);
                bf[nj][1] = __float_as_uint(p[4]);
            }
            #pragma unroll
            for (int mi = 0; mi < 4; mi++)
                #pragma unroll
                for (int nj = 0; nj < 2; nj++)
                    mma8(sacc[mi][nj], af[mi], bf[nj]);
        }

        // ---- softmax piece: p = mask * exp(s/32); partial row sums ----
        #pragma unroll
        for (int mi = 0; mi < 4; mi++) {
            float s0 = 0.f, s1 = 0.f;
            int r0 = wm + mi * 16 + g;
            #pragma unroll
            for (int nj = 0; nj < 2; nj++) {
                int c0 = wn + nj * 8 + 2 * t4;
                float m0v = maskv[c0], m1v = maskv[c0 + 1];
                float p0 = m0v * __expf(sacc[mi][nj][0] * SCALE);
                float p1 = m1v * __expf(sacc[mi][nj][1] * SCALE);
                float p2 = m0v * __expf(sacc[mi][nj][2] * SCALE);
                float p3 = m1v * __expf(sacc[mi][nj][3] * SCALE);
                s0 += p0 + p1;
                s1 += p2 + p3;
                Ps[r0 * ASTR + c0]           = to_tf32(p0);
                Ps[r0 * ASTR + c0 + 1]       = to_tf32(p1);
                Ps[(r0 + 8) * ASTR + c0]     = to_tf32(p2);
                Ps[(r0 + 8) * ASTR + c0 + 1] = to_tf32(p3);
            }
            s0 += __shfl_xor_sync(0xFFFFFFFFu, s0, 1);
            s0 += __shfl_xor_sync(0xFFFFFFFFu, s0, 2);
            s1 += __shfl_xor_sync(0xFFFFFFFFu, s1, 1);
            s1 += __shfl_xor_sync(0xFFFFFFFFu, s1, 2);
            if (t4 == 0) {
                lpart[wnid * 128 + r0]     = s0;
                lpart[wnid * 128 + r0 + 8] = s1;
            }
        }
        __syncthreads();

        if (tid < 128)
            lrun[tid] += lpart[tid] + lpart[128 + tid] + lpart[256 + tid] + lpart[384 + tid];

        // ---- MMA2: O += P V  (A = Ps[m][k], B[k][n] = Vs[key][d]) ----
        #pragma unroll
        for (int ks = 0; ks < 8; ks++) {
            uint32_t af[4][4], bf[2][2];
            #pragma unroll
            for (int mi = 0; mi < 4; mi++) {
                const float* p = &Ps[(wm + mi * 16 + g) * ASTR + ks * 8 + t4];
                af[mi][0] = __float_as_uint(p[0]);
                af[mi][1] = __float_as_uint(p[8 * ASTR]);
                af[mi][2] = __float_as_uint(p[4]);
                af[mi][3] = __float_as_uint(p[8 * ASTR + 4]);
            }
            #pragma unroll
            for (int nj = 0; nj < 2; nj++) {
                bf[nj][0] = __float_as_uint(Vs[(ks * 8 + t4) * ASTR + wn + nj * 8 + g]);
                bf[nj][1] = __float_as_uint(Vs[(ks * 8 + t4 + 4) * ASTR + wn + nj * 8 + g]);
            }
            #pragma unroll
            for (int mi = 0; mi < 4; mi++)
                #pragma unroll
                for (int nj = 0; nj < 2; nj++)
                    mma8(oacc[mi][nj], af[mi], bf[nj]);
        }
        __syncthreads();
    }

    // normalize + store
    #pragma unroll
    for (int mi = 0; mi < 4; mi++) {
        int r0 = wm + mi * 16 + g;
        int r1 = r0 + 8;
        float il0 = 1.f / lrun[r0];
        float il1 = 1.f / lrun[r1];
        #pragma unroll
        for (int nj = 0; nj < 2; nj++) {
            int c0 = wn + nj * 8 + 2 * t4;
            float* p0 = out + ((size_t)bh * SS + q0 + r0) * HD + c0;
            float* p1 = out + ((size_t)bh * SS + q0 + r1) * HD + c0;
            *(float2*)p0 = make_float2(oacc[mi][nj][0] * il0, oacc[mi][nj][1] * il0);
            *(float2*)p1 = make_float2(oacc[mi][nj][2] * il1, oacc[mi][nj][3] * il1);
        }
    }
}

// ---------------------------------------------------------------------------
extern "C" void kernel_launch(void* const* d_in, const int* in_sizes, int n_in,
                              void* d_out, int out_size)
{
    (void)in_sizes; (void)n_in; (void)out_size;
    const float* q  = (const float*)d_in[0];
    const float* k  = (const float*)d_in[1];
    const float* v  = (const float*)d_in[2];
    const int*   am = (const int*)  d_in[3];
    const float* Wq = (const float*)d_in[4];
    const float* bq = (const float*)d_in[5];
    const float* Wk = (const float*)d_in[6];
    const float* bk = (const float*)d_in[7];
    const float* Wv = (const float*)d_in[8];
    const float* bv = (const float*)d_in[9];

    static int attr_set = 0;
    if (!attr_set) {
        cudaFuncSetAttribute(attn_kernel, cudaFuncAttributeMaxDynamicSharedMemorySize,
                             ASM_FLOATS * (int)sizeof(float));
        attr_set = 1;
    }

    dim3 pgrid(EMBED / 128, MROWS / 128, 3);   // (8, 32, 3)
    proj_kernel<<<pgrid, 256>>>(q, k, v, Wq, Wk, Wv, bq, bk, bv);

    dim3 agrid(BHD, SS / 128);                 // (32, 16)
    attn_kernel<<<agrid, 256, ASM_FLOATS * sizeof(float)>>>(am, (float*)d_out);
}

// round 6
// speedup vs baseline: 3.6261x; 1.1806x over previous
#include <cuda_runtime.h>
#include <cstdint>
#include <math.h>

#define EMBED 1024
#define NHEADS 16
#define HD 64
#define BB 2
#define SS 2048
#define BHD (BB*NHEADS)   // 32
#define MROWS (BB*SS)     // 4096
#define SCALE 0.03125f    // 1/sqrt(1024)

// Projected Q,K,V in [B,H,S,D] fp32 (device globals: alloc-guard safe)
__device__ float g_Q[(size_t)BB*NHEADS*SS*HD];
__device__ float g_K[(size_t)BB*NHEADS*SS*HD];
__device__ float g_V[(size_t)BB*NHEADS*SS*HD];

__device__ __forceinline__ float to_tf32(float x) {
    float r;
    asm("cvt.rna.tf32.f32 %0, %1;" : "=f"(r) : "f"(x));
    return r;
}

__device__ __forceinline__ uint32_t smem_u32(const void* p) {
    uint32_t a;
    asm("{ .reg .u64 t; cvta.to.shared.u64 t, %1; cvt.u32.u64 %0, t; }" : "=r"(a) : "l"(p));
    return a;
}

// D = A(16x8 tf32) * B(8x8 tf32) + D, f32 accum. row.col layout.
__device__ __forceinline__ void mma8(float* d, const uint32_t* a, const uint32_t* b) {
    asm volatile(
        "mma.sync.aligned.m16n8k8.row.col.f32.tf32.tf32.f32 "
        "{%0,%1,%2,%3}, {%4,%5,%6,%7}, {%8,%9}, {%0,%1,%2,%3};"
        : "+f"(d[0]), "+f"(d[1]), "+f"(d[2]), "+f"(d[3])
        : "r"(a[0]), "r"(a[1]), "r"(a[2]), "r"(a[3]), "r"(b[0]), "r"(b[1]));
}

// ldmatrix x4 (b16 view of tf32 data: each reg = one 32-bit element)
__device__ __forceinline__ void ldsm_x4(uint32_t* r, uint32_t addr) {
    asm volatile("ldmatrix.sync.aligned.m8n8.x4.shared.b16 {%0,%1,%2,%3}, [%4];"
        : "=r"(r[0]), "=r"(r[1]), "=r"(r[2]), "=r"(r[3]) : "r"(addr));
}

// A-frag address (bytes, /4 in floats): 16x8 tile at row base R, col base ks*8, stride STR floats
// lane mapping: addr row = R + (lane&15), col = ks*8 + (lane>>4)*4
// B-pair address: rows N..N+16 (2 nj tiles): row = N + ((lane>>4)<<3) + (lane&7), col = ks*8 + (((lane>>3)&1)<<2)

// ---------------------------------------------------------------------------
// Kernel 1: QKV projection  y = x @ W^T + b  -> [B,H,S,D]
// BM=BN=128, BK=32. 8 warps as 2x4, warp tile 64x32. ldmatrix fragments.
// ---------------------------------------------------------------------------
#define PSTR 36   // smem row stride (floats): 144B, 144%128=16 -> ldsm conflict-free

__global__ void __launch_bounds__(256) proj_kernel(
    const float* __restrict__ xq, const float* __restrict__ xk, const float* __restrict__ xv,
    const float* __restrict__ Wq, const float* __restrict__ Wk, const float* __restrict__ Wv,
    const float* __restrict__ bq, const float* __restrict__ bk, const float* __restrict__ bv)
{
    __shared__ float As[128 * PSTR];
    __shared__ float Bs[128 * PSTR];
    const uint32_t asb = smem_u32(As);
    const uint32_t bsb = smem_u32(Bs);

    const float* x; const float* W; const float* bias; float* outp;
    int z = blockIdx.z;
    if (z == 0)      { x = xq; W = Wq; bias = bq; outp = g_Q; }
    else if (z == 1) { x = xk; W = Wk; bias = bk; outp = g_K; }
    else             { x = xv; W = Wv; bias = bv; outp = g_V; }

    const int m0 = blockIdx.y * 128;
    const int n0 = blockIdx.x * 128;
    const int tid  = threadIdx.x;
    const int wid  = tid >> 5;
    const int lane = tid & 31;
    const int g    = lane >> 2;
    const int t4   = lane & 3;
    const int wm   = (wid >> 2) * 64;   // 0 or 64
    const int wn   = (wid & 3) * 32;    // 0,32,64,96

    const uint32_t a_l15 = (uint32_t)(lane & 15);
    const uint32_t a_hi4 = (uint32_t)((lane >> 4) << 2);
    const uint32_t b_row = (uint32_t)(((lane >> 4) << 3) + (lane & 7));
    const uint32_t b_c4  = (uint32_t)(((lane >> 3) & 1) << 2);

    float4 ra[4], rb[4];

#define PROJ_LOADG(K0)                                                          \
    {                                                                           \
        _Pragma("unroll")                                                       \
        for (int i = 0; i < 4; i++) {                                           \
            int idx = tid + i * 256;                                            \
            int r = idx >> 3, c4 = idx & 7;                                     \
            ra[i] = *(const float4*)(x + (size_t)(m0 + r) * EMBED + (K0) + c4 * 4); \
            rb[i] = *(const float4*)(W + (size_t)(n0 + r) * EMBED + (K0) + c4 * 4); \
        }                                                                       \
    }

    float acc[4][4][4];
    #pragma unroll
    for (int mi = 0; mi < 4; mi++)
        #pragma unroll
        for (int nj = 0; nj < 4; nj++)
            #pragma unroll
            for (int e = 0; e < 4; e++) acc[mi][nj][e] = 0.f;

    PROJ_LOADG(0);

    for (int c = 0; c < EMBED / 32; c++) {
        #pragma unroll
        for (int i = 0; i < 4; i++) {
            int idx = tid + i * 256;
            int r = idx >> 3, c4 = idx & 7;
            float* pa = &As[r * PSTR + c4 * 4];
            pa[0] = to_tf32(ra[i].x); pa[1] = to_tf32(ra[i].y);
            pa[2] = to_tf32(ra[i].z); pa[3] = to_tf32(ra[i].w);
            float* pb = &Bs[r * PSTR + c4 * 4];
            pb[0] = to_tf32(rb[i].x); pb[1] = to_tf32(rb[i].y);
            pb[2] = to_tf32(rb[i].z); pb[3] = to_tf32(rb[i].w);
        }
        __syncthreads();
        if (c + 1 < EMBED / 32) PROJ_LOADG((c + 1) * 32);

        #pragma unroll
        for (int ks = 0; ks < 4; ks++) {
            uint32_t af[4][4], bf4[2][4];
            #pragma unroll
            for (int mi = 0; mi < 4; mi++)
                ldsm_x4(af[mi], asb + 4u * ((uint32_t)(wm + mi * 16) * PSTR + a_l15 * PSTR
                                            + (uint32_t)(ks * 8) + a_hi4));
            #pragma unroll
            for (int p = 0; p < 2; p++)
                ldsm_x4(bf4[p], bsb + 4u * ((uint32_t)(wn + p * 16) * PSTR + b_row * PSTR
                                            + (uint32_t)(ks * 8) + b_c4));
            #pragma unroll
            for (int mi = 0; mi < 4; mi++)
                #pragma unroll
                for (int nj = 0; nj < 4; nj++)
                    mma8(acc[mi][nj], af[mi], &bf4[nj >> 1][(nj & 1) * 2]);
        }
        __syncthreads();
    }

    // epilogue: +bias, scatter to [B,H,S,D]
    #pragma unroll
    for (int mi = 0; mi < 4; mi++) {
        int r0 = m0 + wm + mi * 16 + g;
        int r1 = r0 + 8;
        int bb0 = r0 >> 11, s0 = r0 & 2047;
        int bb1 = r1 >> 11, s1 = r1 & 2047;
        #pragma unroll
        for (int nj = 0; nj < 4; nj++) {
            int f = n0 + wn + nj * 8 + 2 * t4;
            int h = f >> 6, dd = f & 63;
            float b0 = bias[f], b1 = bias[f + 1];
            float* p0 = outp + (((size_t)(bb0 * NHEADS + h)) * SS + s0) * HD + dd;
            float* p1 = outp + (((size_t)(bb1 * NHEADS + h)) * SS + s1) * HD + dd;
            *(float2*)p0 = make_float2(acc[mi][nj][0] + b0, acc[mi][nj][1] + b1);
            *(float2*)p1 = make_float2(acc[mi][nj][2] + b0, acc[mi][nj][3] + b1);
        }
    }
}

// ---------------------------------------------------------------------------
// Kernel 2: attention. 128 threads (4 warps), q-tile 128, warp tile 32x64.
// Q fragments register-resident; P permuted acc->A-frag via shfl (no Ps smem);
// row sums in registers across the whole loop.
// ---------------------------------------------------------------------------
#define ASTR 68   // Qs/Ks stride (272B, %128=16: ldsm conflict-free)
#define VSTR 72   // Vs stride (288B, %128=32: scalar B loads conflict-free)

#define OFF_K  (128 * ASTR)            // 8704
#define OFF_V  (OFF_K + 64 * ASTR)     // 13056
#define OFF_MK (OFF_V + 64 * VSTR)     // 17664
#define ASM_FLOATS (OFF_MK + 64)       // 17728 floats = 70912 B

__global__ void __launch_bounds__(128, 2) attn_kernel(const int* __restrict__ amask,
                                                      float* __restrict__ out)
{
    extern __shared__ float sm[];
    float* Qs    = sm;
    float* Ks    = sm + OFF_K;
    float* Vs    = sm + OFF_V;
    float* maskv = sm + OFF_MK;
    const uint32_t qsb = smem_u32(sm);
    const uint32_t ksb = qsb + OFF_K * 4;

    const int tid  = threadIdx.x;
    const int wid  = tid >> 5;
    const int lane = tid & 31;
    const int g    = lane >> 2;
    const int t4   = lane & 3;
    const int wm   = wid * 32;

    const uint32_t a_l15 = (uint32_t)(lane & 15);
    const uint32_t a_hi4 = (uint32_t)((lane >> 4) << 2);
    const uint32_t b_row = (uint32_t)(((lane >> 4) << 3) + (lane & 7));
    const uint32_t b_c4  = (uint32_t)(((lane >> 3) & 1) << 2);

    const int bh = blockIdx.x;
    const int b  = bh >> 4;
    const int q0 = blockIdx.y * 128;

    const float* Qb = g_Q + (size_t)bh * SS * HD;
    const float* Kb = g_K + (size_t)bh * SS * HD;
    const float* Vb = g_V + (size_t)bh * SS * HD;

    // ---- stage Q tile [128x64], then load resident fragments ----
    #pragma unroll
    for (int i = 0; i < 16; i++) {
        int idx = tid + i * 128;
        int r = idx >> 4, c4 = idx & 15;
        float4 q = *(const float4*)(Qb + (size_t)(q0 + r) * HD + c4 * 4);
        float* p = &Qs[r * ASTR + c4 * 4];
        p[0] = to_tf32(q.x); p[1] = to_tf32(q.y);
        p[2] = to_tf32(q.z); p[3] = to_tf32(q.w);
    }
    __syncthreads();

    uint32_t qf[2][8][4];
    #pragma unroll
    for (int mi = 0; mi < 2; mi++)
        #pragma unroll
        for (int ks = 0; ks < 8; ks++)
            ldsm_x4(qf[mi][ks], qsb + 4u * ((uint32_t)(wm + mi * 16) * ASTR + a_l15 * ASTR
                                            + (uint32_t)(ks * 8) + a_hi4));

    float oacc[2][8][4];
    #pragma unroll
    for (int mi = 0; mi < 2; mi++)
        #pragma unroll
        for (int nj = 0; nj < 8; nj++)
            #pragma unroll
            for (int e = 0; e < 4; e++) oacc[mi][nj][e] = 0.f;
    float lrA[2] = {0.f, 0.f}, lrB[2] = {0.f, 0.f};

    const int srcA = (lane & 28) | (t4 >> 1);
    const int srcB = srcA + 2;
    const bool odd = (t4 & 1) != 0;

    for (int kt = 0; kt < SS / 64; kt++) {
        const int k0 = kt * 64;
        __syncthreads();   // previous iter done reading Ks/Vs

        #pragma unroll
        for (int i = 0; i < 8; i++) {
            int idx = tid + i * 128;
            int r = idx >> 4, c4 = idx & 15;
            float4 kk = *(const float4*)(Kb + (size_t)(k0 + r) * HD + c4 * 4);
            float4 vv = *(const float4*)(Vb + (size_t)(k0 + r) * HD + c4 * 4);
            float* pk = &Ks[r * ASTR + c4 * 4];
            pk[0] = to_tf32(kk.x); pk[1] = to_tf32(kk.y);
            pk[2] = to_tf32(kk.z); pk[3] = to_tf32(kk.w);
            float* pv = &Vs[r * VSTR + c4 * 4];
            pv[0] = to_tf32(vv.x); pv[1] = to_tf32(vv.y);
            pv[2] = to_tf32(vv.z); pv[3] = to_tf32(vv.w);
        }
        if (tid < 64)
            maskv[tid] = (amask[(size_t)b * SS + k0 + tid] != 0) ? 1.f : 0.f;
        __syncthreads();

        // ---- MMA1: S[32x64] = Q K^T  (A resident, B via ldmatrix) ----
        float sa[2][8][4];
        #pragma unroll
        for (int mi = 0; mi < 2; mi++)
            #pragma unroll
            for (int nj = 0; nj < 8; nj++)
                #pragma unroll
                for (int e = 0; e < 4; e++) sa[mi][nj][e] = 0.f;

        #pragma unroll
        for (int ks = 0; ks < 8; ks++) {
            uint32_t bq[4][4];
            #pragma unroll
            for (int p = 0; p < 4; p++)
                ldsm_x4(bq[p], ksb + 4u * ((uint32_t)(p * 16) * ASTR + b_row * ASTR
                                           + (uint32_t)(ks * 8) + b_c4));
            #pragma unroll
            for (int mi = 0; mi < 2; mi++)
                #pragma unroll
                for (int nj = 0; nj < 8; nj++)
                    mma8(sa[mi][nj], qf[mi][ks], &bq[nj >> 1][(nj & 1) * 2]);
        }

        // ---- softmax piece: p = mask * exp(s/32); row sums in regs ----
        #pragma unroll
        for (int nj = 0; nj < 8; nj++) {
            float m0 = maskv[nj * 8 + 2 * t4];
            float m1 = maskv[nj * 8 + 2 * t4 + 1];
            #pragma unroll
            for (int mi = 0; mi < 2; mi++) {
                float p0 = m0 * __expf(sa[mi][nj][0] * SCALE);
                float p1 = m1 * __expf(sa[mi][nj][1] * SCALE);
                float p2 = m0 * __expf(sa[mi][nj][2] * SCALE);
                float p3 = m1 * __expf(sa[mi][nj][3] * SCALE);
                sa[mi][nj][0] = p0; sa[mi][nj][1] = p1;
                sa[mi][nj][2] = p2; sa[mi][nj][3] = p3;
                lrA[mi] += p0 + p1;
                lrB[mi] += p2 + p3;
            }
        }

        // ---- MMA2: O += P V  (A from shfl-permuted regs, B scalar from Vs) ----
        #pragma unroll
        for (int ks = 0; ks < 8; ks++) {
            uint32_t pa[2][4];
            #pragma unroll
            for (int mi = 0; mi < 2; mi++) {
                float v0 = __shfl_sync(0xFFFFFFFFu, sa[mi][ks][0], srcA);
                float v1 = __shfl_sync(0xFFFFFFFFu, sa[mi][ks][1], srcA);
                float v2 = __shfl_sync(0xFFFFFFFFu, sa[mi][ks][2], srcA);
                float v3 = __shfl_sync(0xFFFFFFFFu, sa[mi][ks][3], srcA);
                float w0 = __shfl_sync(0xFFFFFFFFu, sa[mi][ks][0], srcB);
                float w1 = __shfl_sync(0xFFFFFFFFu, sa[mi][ks][1], srcB);
                float w2 = __shfl_sync(0xFFFFFFFFu, sa[mi][ks][2], srcB);
                float w3 = __shfl_sync(0xFFFFFFFFu, sa[mi][ks][3], srcB);
                pa[mi][0] = __float_as_uint(to_tf32(odd ? v1 : v0));
                pa[mi][1] = __float_as_uint(to_tf32(odd ? v3 : v2));
                pa[mi][2] = __float_as_uint(to_tf32(odd ? w1 : w0));
                pa[mi][3] = __float_as_uint(to_tf32(odd ? w3 : w2));
            }
            #pragma unroll
            for (int nj = 0; nj < 8; nj++) {
                uint32_t bv[2];
                bv[0] = __float_as_uint(Vs[(ks * 8 + t4) * VSTR + nj * 8 + g]);
                bv[1] = __float_as_uint(Vs[(ks * 8 + t4 + 4) * VSTR + nj * 8 + g]);
                mma8(oacc[0][nj], pa[0], bv);
                mma8(oacc[1][nj], pa[1], bv);
            }
        }
    }

    // ---- reduce row sums across quad, normalize, store ----
    #pragma unroll
    for (int mi = 0; mi < 2; mi++) {
        lrA[mi] += __shfl_xor_sync(0xFFFFFFFFu, lrA[mi], 1);
        lrA[mi] += __shfl_xor_sync(0xFFFFFFFFu, lrA[mi], 2);
        lrB[mi] += __shfl_xor_sync(0xFFFFFFFFu, lrB[mi], 1);
        lrB[mi] += __shfl_xor_sync(0xFFFFFFFFu, lrB[mi], 2);
    }

    #pragma unroll
    for (int mi = 0; mi < 2; mi++) {
        int r0 = wm + mi * 16 + g;
        int r1 = r0 + 8;
        float il0 = 1.f / lrA[mi];
        float il1 = 1.f / lrB[mi];
        #pragma unroll
        for (int nj = 0; nj < 8; nj++) {
            int c0 = nj * 8 + 2 * t4;
            float* p0 = out + ((size_t)bh * SS + q0 + r0) * HD + c0;
            float* p1 = out + ((size_t)bh * SS + q0 + r1) * HD + c0;
            *(float2*)p0 = make_float2(oacc[mi][nj][0] * il0, oacc[mi][nj][1] * il0);
            *(float2*)p1 = make_float2(oacc[mi][nj][2] * il1, oacc[mi][nj][3] * il1);
        }
    }
}

// ---------------------------------------------------------------------------
extern "C" void kernel_launch(void* const* d_in, const int* in_sizes, int n_in,
                              void* d_out, int out_size)
{
    (void)in_sizes; (void)n_in; (void)out_size;
    const float* q  = (const float*)d_in[0];
    const float* k  = (const float*)d_in[1];
    const float* v  = (const float*)d_in[2];
    const int*   am = (const int*)  d_in[3];
    const float* Wq = (const float*)d_in[4];
    const float* bq = (const float*)d_in[5];
    const float* Wk = (const float*)d_in[6];
    const float* bk = (const float*)d_in[7];
    const float* Wv = (const float*)d_in[8];
    const float* bv = (const float*)d_in[9];

    static int attr_set = 0;
    if (!attr_set) {
        cudaFuncSetAttribute(attn_kernel, cudaFuncAttributeMaxDynamicSharedMemorySize,
                             ASM_FLOATS * (int)sizeof(float));
        attr_set = 1;
    }

    dim3 pgrid(EMBED / 128, MROWS / 128, 3);   // (8, 32, 3)
    proj_kernel<<<pgrid, 256>>>(q, k, v, Wq, Wk, Wv, bq, bk, bv);

    dim3 agrid(BHD, SS / 128);                 // (32, 16)
    attn_kernel<<<agrid, 128, ASM_FLOATS * sizeof(float)>>>(am, (float*)d_out);
}

// round 8
// speedup vs baseline: 3.8388x; 1.0587x over previous
#include <cuda_runtime.h>
#include <cstdint>
#include <math.h>

#define EMBED 1024
#define NHEADS 16
#define HD 64
#define BB 2
#define SS 2048
#define BHD (BB*NHEADS)   // 32
#define MROWS (BB*SS)     // 4096
#define SCALE 0.03125f    // 1/sqrt(1024)

// Projected Q,K,V in [B,H,S,D], pre-rounded to tf32 values (device globals)
__device__ float g_Q[(size_t)BB*NHEADS*SS*HD];
__device__ float g_K[(size_t)BB*NHEADS*SS*HD];
__device__ float g_V[(size_t)BB*NHEADS*SS*HD];

__device__ __forceinline__ float to_tf32(float x) {
    float r;
    asm("cvt.rna.tf32.f32 %0, %1;" : "=f"(r) : "f"(x));
    return r;
}

__device__ __forceinline__ uint32_t smem_u32(const void* p) {
    uint32_t a;
    asm("{ .reg .u64 t; cvta.to.shared.u64 t, %1; cvt.u32.u64 %0, t; }" : "=r"(a) : "l"(p));
    return a;
}

// D = A(16x8 tf32) * B(8x8 tf32) + D, f32 accum. row.col layout.
__device__ __forceinline__ void mma8(float* d, const uint32_t* a, const uint32_t* b) {
    asm volatile(
        "mma.sync.aligned.m16n8k8.row.col.f32.tf32.tf32.f32 "
        "{%0,%1,%2,%3}, {%4,%5,%6,%7}, {%8,%9}, {%0,%1,%2,%3};"
        : "+f"(d[0]), "+f"(d[1]), "+f"(d[2]), "+f"(d[3])
        : "r"(a[0]), "r"(a[1]), "r"(a[2]), "r"(a[3]), "r"(b[0]), "r"(b[1]));
}

// ldmatrix x4 (b16 view of tf32 data: each reg = one 32-bit element)
__device__ __forceinline__ void ldsm_x4(uint32_t* r, uint32_t addr) {
    asm volatile("ldmatrix.sync.aligned.m8n8.x4.shared.b16 {%0,%1,%2,%3}, [%4];"
        : "=r"(r[0]), "=r"(r[1]), "=r"(r[2]), "=r"(r[3]) : "r"(addr));
}

// cp.async helpers
__device__ __forceinline__ void cp16(uint32_t dst, const void* src) {
    asm volatile("cp.async.cg.shared.global [%0], [%1], 16;" :: "r"(dst), "l"(src));
}
__device__ __forceinline__ void cp4(uint32_t dst, const void* src) {
    asm volatile("cp.async.ca.shared.global [%0], [%1], 4;" :: "r"(dst), "l"(src));
}
#define CP_COMMIT() asm volatile("cp.async.commit_group;" ::: "memory")
#define CP_WAIT0()  asm volatile("cp.async.wait_group 0;" ::: "memory")

// ---------------------------------------------------------------------------
// Kernel 1: QKV projection  y = tf32_round(x @ W^T + b)  -> [B,H,S,D]
// BM=BN=128, BK=32. 8 warps as 2x4, warp tile 64x32.
// Double-buffered smem, ONE barrier per chunk, register prefetch.
// ---------------------------------------------------------------------------
#define PSTR 36            // smem row stride (floats): 144B, %128=16 -> ldsm conflict-free
#define PBUF (2*128*PSTR)  // floats per buffer (A+B)
#define PROJ_SMEM_BYTES (2 * PBUF * 4)   // 73728

__global__ void __launch_bounds__(256) proj_kernel(
    const float* __restrict__ xq, const float* __restrict__ xk, const float* __restrict__ xv,
    const float* __restrict__ Wq, const float* __restrict__ Wk, const float* __restrict__ Wv,
    const float* __restrict__ bq, const float* __restrict__ bk, const float* __restrict__ bv)
{
    extern __shared__ float psm[];
    const uint32_t base = smem_u32(psm);

    const float* x; const float* W; const float* bias; float* outp;
    int z = blockIdx.z;
    if (z == 0)      { x = xq; W = Wq; bias = bq; outp = g_Q; }
    else if (z == 1) { x = xk; W = Wk; bias = bk; outp = g_K; }
    else             { x = xv; W = Wv; bias = bv; outp = g_V; }

    const int m0 = blockIdx.y * 128;
    const int n0 = blockIdx.x * 128;
    const int tid  = threadIdx.x;
    const int wid  = tid >> 5;
    const int lane = tid & 31;
    const int g    = lane >> 2;
    const int t4   = lane & 3;
    const int wm   = (wid >> 2) * 64;   // 0 or 64
    const int wn   = (wid & 3) * 32;    // 0,32,64,96

    const uint32_t a_l15 = (uint32_t)(lane & 15);
    const uint32_t a_hi4 = (uint32_t)((lane >> 4) << 2);
    const uint32_t b_row = (uint32_t)(((lane >> 4) << 3) + (lane & 7));
    const uint32_t b_c4  = (uint32_t)(((lane >> 3) & 1) << 2);

    float4 ra[4], rb[4];

#define PROJ_LOADG(K0)                                                          \
    {                                                                           \
        _Pragma("unroll")                                                       \
        for (int i = 0; i < 4; i++) {                                           \
            int idx = tid + i * 256;                                            \
            int r = idx >> 3, c4 = idx & 7;                                     \
            ra[i] = *(const float4*)(x + (size_t)(m0 + r) * EMBED + (K0) + c4 * 4); \
            rb[i] = *(const float4*)(W + (size_t)(n0 + r) * EMBED + (K0) + c4 * 4); \
        }                                                                       \
    }

    float acc[4][4][4];
    #pragma unroll
    for (int mi = 0; mi < 4; mi++)
        #pragma unroll
        for (int nj = 0; nj < 4; nj++)
            #pragma unroll
            for (int e = 0; e < 4; e++) acc[mi][nj][e] = 0.f;

    PROJ_LOADG(0);

    for (int c = 0; c < EMBED / 32; c++) {
        const int buf = c & 1;
        float* As = psm + buf * PBUF;
        float* Bs = As + 128 * PSTR;
        #pragma unroll
        for (int i = 0; i < 4; i++) {
            int idx = tid + i * 256;
            int r = idx >> 3, c4 = idx & 7;
            float* pa = &As[r * PSTR + c4 * 4];
            pa[0] = to_tf32(ra[i].x); pa[1] = to_tf32(ra[i].y);
            pa[2] = to_tf32(ra[i].z); pa[3] = to_tf32(ra[i].w);
            float* pb = &Bs[r * PSTR + c4 * 4];
            pb[0] = to_tf32(rb[i].x); pb[1] = to_tf32(rb[i].y);
            pb[2] = to_tf32(rb[i].z); pb[3] = to_tf32(rb[i].w);
        }
        if (c + 1 < EMBED / 32) PROJ_LOADG((c + 1) * 32);
        __syncthreads();

        const uint32_t asb = base + (uint32_t)(buf * PBUF) * 4u;
        const uint32_t bsb = asb + 128u * PSTR * 4u;
        #pragma unroll
        for (int ks = 0; ks < 4; ks++) {
            uint32_t af[4][4], bf4[2][4];
            #pragma unroll
            for (int mi = 0; mi < 4; mi++)
                ldsm_x4(af[mi], asb + 4u * ((uint32_t)(wm + mi * 16) * PSTR + a_l15 * PSTR
                                            + (uint32_t)(ks * 8) + a_hi4));
            #pragma unroll
            for (int p = 0; p < 2; p++)
                ldsm_x4(bf4[p], bsb + 4u * ((uint32_t)(wn + p * 16) * PSTR + b_row * PSTR
                                            + (uint32_t)(ks * 8) + b_c4));
            #pragma unroll
            for (int mi = 0; mi < 4; mi++)
                #pragma unroll
                for (int nj = 0; nj < 4; nj++)
                    mma8(acc[mi][nj], af[mi], &bf4[nj >> 1][(nj & 1) * 2]);
        }
    }

    // epilogue: +bias, tf32-round, scatter to [B,H,S,D]
    #pragma unroll
    for (int mi = 0; mi < 4; mi++) {
        int r0 = m0 + wm + mi * 16 + g;
        int r1 = r0 + 8;
        int bb0 = r0 >> 11, s0 = r0 & 2047;
        int bb1 = r1 >> 11, s1 = r1 & 2047;
        #pragma unroll
        for (int nj = 0; nj < 4; nj++) {
            int f = n0 + wn + nj * 8 + 2 * t4;
            int h = f >> 6, dd = f & 63;
            float b0 = bias[f], b1 = bias[f + 1];
            float* p0 = outp + (((size_t)(bb0 * NHEADS + h)) * SS + s0) * HD + dd;
            float* p1 = outp + (((size_t)(bb1 * NHEADS + h)) * SS + s1) * HD + dd;
            *(float2*)p0 = make_float2(to_tf32(acc[mi][nj][0] + b0), to_tf32(acc[mi][nj][1] + b1));
            *(float2*)p1 = make_float2(to_tf32(acc[mi][nj][2] + b0), to_tf32(acc[mi][nj][3] + b1));
        }
    }
}

// ---------------------------------------------------------------------------
// Kernel 2: attention. 128 threads (4 warps), q-tile 128, warp tile 32x64.
// cp.async double-buffered K/V staging (raw copies; data pre-rounded to tf32),
// Q fragments register-resident, P permuted acc->A-frag via shfl,
// row sums register-resident.
// ---------------------------------------------------------------------------
#define ASTR 68   // Qs/Ks stride (272B, %128=16: ldsm conflict-free)
#define VSTR 72   // Vs stride (288B, %128=32: scalar B loads conflict-free)

#define OFF_K  (128 * ASTR)              // 8704
#define OFF_V  (OFF_K + 2 * 64 * ASTR)   // 17408
#define OFF_MK (OFF_V + 2 * 64 * VSTR)   // 26624 (ints)
#define ASM_FLOATS (OFF_MK + 128)        // 26752 floats = 107008 B

__global__ void __launch_bounds__(128, 2) attn_kernel(const int* __restrict__ amask,
                                                      float* __restrict__ out)
{
    extern __shared__ float sm[];
    float* Qs = sm;
    const uint32_t qsb = smem_u32(sm);

    const int tid  = threadIdx.x;
    const int wid  = tid >> 5;
    const int lane = tid & 31;
    const int g    = lane >> 2;
    const int t4   = lane & 3;
    const int wm   = wid * 32;

    const uint32_t a_l15 = (uint32_t)(lane & 15);
    const uint32_t a_hi4 = (uint32_t)((lane >> 4) << 2);
    const uint32_t b_row = (uint32_t)(((lane >> 4) << 3) + (lane & 7));
    const uint32_t b_c4  = (uint32_t)(((lane >> 3) & 1) << 2);

    const int bh = blockIdx.x;
    const int b  = bh >> 4;
    const int q0 = blockIdx.y * 128;

    const float* Qb = g_Q + (size_t)bh * SS * HD;
    const float* Kb = g_K + (size_t)bh * SS * HD;
    const float* Vb = g_V + (size_t)bh * SS * HD;

    // ---- stage Q tile [128x64] (persistent; already tf32 values) ----
    #pragma unroll
    for (int i = 0; i < 16; i++) {
        int idx = tid + i * 128;
        int r = idx >> 4, c4 = idx & 15;
        *(float4*)&Qs[r * ASTR + c4 * 4] = *(const float4*)(Qb + (size_t)(q0 + r) * HD + c4 * 4);
    }

    // issue tile KT's K/V/mask copies into buffer BUF
#define ISSUE_TILE(KT, BUF)                                                     \
    {                                                                           \
        const int k0_ = (KT) * 64;                                              \
        const uint32_t kb_ = qsb + 4u * (uint32_t)(OFF_K + (BUF) * 64 * ASTR);  \
        const uint32_t vb_ = qsb + 4u * (uint32_t)(OFF_V + (BUF) * 64 * VSTR);  \
        _Pragma("unroll")                                                       \
        for (int i = 0; i < 8; i++) {                                           \
            int idx = tid + i * 128;                                            \
            int r = idx >> 4, c4 = idx & 15;                                    \
            cp16(kb_ + 4u * (uint32_t)(r * ASTR + c4 * 4),                      \
                 Kb + (size_t)(k0_ + r) * HD + c4 * 4);                         \
            cp16(vb_ + 4u * (uint32_t)(r * VSTR + c4 * 4),                      \
                 Vb + (size_t)(k0_ + r) * HD + c4 * 4);                         \
        }                                                                       \
        if (tid < 64)                                                           \
            cp4(qsb + 4u * (uint32_t)(OFF_MK + (BUF) * 64 + tid),               \
                amask + (size_t)b * SS + k0_ + tid);                            \
        CP_COMMIT();                                                            \
    }

    ISSUE_TILE(0, 0);

    // ---- resident Q fragments ----
    __syncthreads();   // Qs visible to all warps before ldsm
    uint32_t qf[2][8][4];
    #pragma unroll
    for (int mi = 0; mi < 2; mi++)
        #pragma unroll
        for (int ks = 0; ks < 8; ks++)
            ldsm_x4(qf[mi][ks], qsb + 4u * ((uint32_t)(wm + mi * 16) * ASTR + a_l15 * ASTR
                                            + (uint32_t)(ks * 8) + a_hi4));

    float oacc[2][8][4];
    #pragma unroll
    for (int mi = 0; mi < 2; mi++)
        #pragma unroll
        for (int nj = 0; nj < 8; nj++)
            #pragma unroll
            for (int e = 0; e < 4; e++) oacc[mi][nj][e] = 0.f;
    float lrA[2] = {0.f, 0.f}, lrB[2] = {0.f, 0.f};

    const int srcA = (lane & 28) | (t4 >> 1);
    const int srcB = srcA + 2;
    const bool odd = (t4 & 1) != 0;

    for (int kt = 0; kt < SS / 64; kt++) {
        const int buf = kt & 1;

        CP_WAIT0();        // tile kt's copies (this thread's) complete
        __syncthreads();   // all threads' copies visible; compute(kt-1) reads done

        if (kt + 1 < SS / 64) ISSUE_TILE(kt + 1, buf ^ 1);

        const uint32_t ksb = qsb + 4u * (uint32_t)(OFF_K + buf * 64 * ASTR);
        const float*   Vs  = sm + OFF_V + buf * 64 * VSTR;
        const int*     mki = (const int*)(sm + OFF_MK) + buf * 64;

        // ---- MMA1: S[32x64] = Q K^T ----
        float sa[2][8][4];
        #pragma unroll
        for (int mi = 0; mi < 2; mi++)
            #pragma unroll
            for (int nj = 0; nj < 8; nj++)
                #pragma unroll
                for (int e = 0; e < 4; e++) sa[mi][nj][e] = 0.f;

        #pragma unroll
        for (int ks = 0; ks < 8; ks++) {
            uint32_t bq[4][4];
            #pragma unroll
            for (int p = 0; p < 4; p++)
                ldsm_x4(bq[p], ksb + 4u * ((uint32_t)(p * 16) * ASTR + b_row * ASTR
                                           + (uint32_t)(ks * 8) + b_c4));
            #pragma unroll
            for (int mi = 0; mi < 2; mi++)
                #pragma unroll
                for (int nj = 0; nj < 8; nj++)
                    mma8(sa[mi][nj], qf[mi][ks], &bq[nj >> 1][(nj & 1) * 2]);
        }

        // ---- softmax piece: p = mask ? exp(s/32) : 0; row sums in regs ----
        #pragma unroll
        for (int nj = 0; nj < 8; nj++) {
            bool m0 = mki[nj * 8 + 2 * t4] != 0;
            bool m1 = mki[nj * 8 + 2 * t4 + 1] != 0;
            #pragma unroll
            for (int mi = 0; mi < 2; mi++) {
                float p0 = m0 ? __expf(sa[mi][nj][0] * SCALE) : 0.f;
                float p1 = m1 ? __expf(sa[mi][nj][1] * SCALE) : 0.f;
                float p2 = m0 ? __expf(sa[mi][nj][2] * SCALE) : 0.f;
                float p3 = m1 ? __expf(sa[mi][nj][3] * SCALE) : 0.f;
                sa[mi][nj][0] = p0; sa[mi][nj][1] = p1;
                sa[mi][nj][2] = p2; sa[mi][nj][3] = p3;
                lrA[mi] += p0 + p1;
                lrB[mi] += p2 + p3;
            }
        }

        // ---- MMA2: O += P V  (A from shfl-permuted regs, B scalar from Vs) ----
        #pragma unroll
        for (int ks = 0; ks < 8; ks++) {
            uint32_t pa[2][4];
            #pragma unroll
            for (int mi = 0; mi < 2; mi++) {
                float v0 = __shfl_sync(0xFFFFFFFFu, sa[mi][ks][0], srcA);
                float v1 = __shfl_sync(0xFFFFFFFFu, sa[mi][ks][1], srcA);
                float v2 = __shfl_sync(0xFFFFFFFFu, sa[mi][ks][2], srcA);
                float v3 = __shfl_sync(0xFFFFFFFFu, sa[mi][ks][3], srcA);
                float w0 = __shfl_sync(0xFFFFFFFFu, sa[mi][ks][0], srcB);
                float w1 = __shfl_sync(0xFFFFFFFFu, sa[mi][ks][1], srcB);
                float w2 = __shfl_sync(0xFFFFFFFFu, sa[mi][ks][2], srcB);
                float w3 = __shfl_sync(0xFFFFFFFFu, sa[mi][ks][3], srcB);
                pa[mi][0] = __float_as_uint(to_tf32(odd ? v1 : v0));
                pa[mi][1] = __float_as_uint(to_tf32(odd ? v3 : v2));
                pa[mi][2] = __float_as_uint(to_tf32(odd ? w1 : w0));
                pa[mi][3] = __float_as_uint(to_tf32(odd ? w3 : w2));
            }
            #pragma unroll
            for (int nj = 0; nj < 8; nj++) {
                uint32_t bv[2];
                bv[0] = __float_as_uint(Vs[(ks * 8 + t4) * VSTR + nj * 8 + g]);
                bv[1] = __float_as_uint(Vs[(ks * 8 + t4 + 4) * VSTR + nj * 8 + g]);
                mma8(oacc[0][nj], pa[0], bv);
                mma8(oacc[1][nj], pa[1], bv);
            }
        }

        __syncthreads();   // all warps done reading buf before next iter overwrites
    }

    // ---- reduce row sums across quad, normalize, store ----
    #pragma unroll
    for (int mi = 0; mi < 2; mi++) {
        lrA[mi] += __shfl_xor_sync(0xFFFFFFFFu, lrA[mi], 1);
        lrA[mi] += __shfl_xor_sync(0xFFFFFFFFu, lrA[mi], 2);
        lrB[mi] += __shfl_xor_sync(0xFFFFFFFFu, lrB[mi], 1);
        lrB[mi] += __shfl_xor_sync(0xFFFFFFFFu, lrB[mi], 2);
    }

    #pragma unroll
    for (int mi = 0; mi < 2; mi++) {
        int r0 = wm + mi * 16 + g;
        int r1 = r0 + 8;
        float il0 = 1.f / lrA[mi];
        float il1 = 1.f / lrB[mi];
        #pragma unroll
        for (int nj = 0; nj < 8; nj++) {
            int c0 = nj * 8 + 2 * t4;
            float* p0 = out + ((size_t)bh * SS + q0 + r0) * HD + c0;
            float* p1 = out + ((size_t)bh * SS + q0 + r1) * HD + c0;
            *(float2*)p0 = make_float2(oacc[mi][nj][0] * il0, oacc[mi][nj][1] * il0);
            *(float2*)p1 = make_float2(oacc[mi][nj][2] * il1, oacc[mi][nj][3] * il1);
        }
    }
}

// ---------------------------------------------------------------------------
extern "C" void kernel_launch(void* const* d_in, const int* in_sizes, int n_in,
                              void* d_out, int out_size)
{
    (void)in_sizes; (void)n_in; (void)out_size;
    const float* q  = (const float*)d_in[0];
    const float* k  = (const float*)d_in[1];
    const float* v  = (const float*)d_in[2];
    const int*   am = (const int*)  d_in[3];
    const float* Wq = (const float*)d_in[4];
    const float* bq = (const float*)d_in[5];
    const float* Wk = (const float*)d_in[6];
    const float* bk = (const float*)d_in[7];
    const float* Wv = (const float*)d_in[8];
    const float* bv = (const float*)d_in[9];

    static int attr_set = 0;
    if (!attr_set) {
        cudaFuncSetAttribute(attn_kernel, cudaFuncAttributeMaxDynamicSharedMemorySize,
                             ASM_FLOATS * (int)sizeof(float));
        cudaFuncSetAttribute(proj_kernel, cudaFuncAttributeMaxDynamicSharedMemorySize,
                             PROJ_SMEM_BYTES);
        attr_set = 1;
    }

    dim3 pgrid(EMBED / 128, MROWS / 128, 3);   // (8, 32, 3)
    proj_kernel<<<pgrid, 256, PROJ_SMEM_BYTES>>>(q, k, v, Wq, Wk, Wv, bq, bk, bv);

    dim3 agrid(BHD, SS / 128);                 // (32, 16)
    attn_kernel<<<agrid, 128, ASM_FLOATS * sizeof(float)>>>(am, (float*)d_out);
}